// round 6
// baseline (speedup 1.0000x reference)
#include <cuda_runtime.h>
#include <cstdint>

// Table-batched embedding bag, SUM pooling.
// indices: int32 [T*B*L], offsets: int32 [T*B+1], weights: fp32 [T*E, 128],
// hash_size_cumsum: int32 [T+1], out: fp32 [B, T*128]
//
// One warp per bag; lane = one float4 (16B) of the 512B row.
// Row gathers via cp.async.cg into per-warp smem staging (zero data regs).
// Depth-2 pipeline: while consuming one group of 4 rows, the next group of 4
// is already in flight -> no dead time between waves.
// __launch_bounds__(256,7) forces regs<=36 so 7 blocks/SM co-reside (87% occ).

#define EMB_D    128
#define GRP      4            // rows per pipeline group
#define WARPS_PB 8            // 256 threads/block; smem = 8*8*512B = 32KB

__global__ void __launch_bounds__(256, 7) tbe_fwd_kernel(
    const int*   __restrict__ indices,
    const int*   __restrict__ offsets,
    const float* __restrict__ weights,
    const int*   __restrict__ hsc,
    float*       __restrict__ out,
    int batch, int n_tables, int num_bags)
{
    // 8 warps * 2 parities * 4 slots * 32 lanes * 16B = 32 KB
    __shared__ float4 buf[WARPS_PB * 2 * GRP * 32];

    const int warp_global = (blockIdx.x * blockDim.x + threadIdx.x) >> 5;
    const int lane = threadIdx.x & 31;
    const int wib  = (threadIdx.x >> 5);
    if (warp_global >= num_bags) return;

    float4* mybuf = buf + wib * (2 * GRP * 32) + lane;   // slot s at mybuf[s*32]
    const unsigned sbase = (unsigned)__cvta_generic_to_shared(mybuf);

    const int seg   = warp_global;
    const int table = seg / batch;
    const int b     = seg - table * batch;

    const int base  = hsc[table];          // T*E <= 4M, fits int32
    const int start = offsets[seg];
    const int end   = offsets[seg + 1];

    const float4* __restrict__ wv = reinterpret_cast<const float4*>(weights);

    float4 a0 = make_float4(0.f, 0.f, 0.f, 0.f);
    float4 a1 = make_float4(0.f, 0.f, 0.f, 0.f);
    float4 a2 = make_float4(0.f, 0.f, 0.f, 0.f);
    float4 a3 = make_float4(0.f, 0.f, 0.f, 0.f);

    for (int chunk = start; chunk < end; chunk += 32) {
        const int cnt = min(32, end - chunk);
        // one coalesced index load for up to 32 bag entries
        const int myidx = (lane < cnt) ? indices[chunk + lane] : 0;

        const int ngroups = (cnt + GRP - 1) >> 2;

        // ---- issue group 0 (parity 0) ----
        #pragma unroll
        for (int j = 0; j < GRP; j++) {
            if (j < cnt) {
                const unsigned row =
                    (unsigned)(__shfl_sync(0xffffffffu, myidx, j) + base);
                asm volatile("cp.async.cg.shared.global [%0], [%1], 16;\n"
                             :: "r"(sbase + j * 512u),
                                "l"(wv + (size_t)row * 32u + lane));
            }
        }
        asm volatile("cp.async.commit_group;\n");

        // ---- steady state: issue g, wait, consume g-1 ----
        for (int g = 1; g < ngroups; g++) {
            const int par = g & 1;
            const int kb  = g * GRP;
            #pragma unroll
            for (int j = 0; j < GRP; j++) {
                if (kb + j < cnt) {
                    const unsigned row =
                        (unsigned)(__shfl_sync(0xffffffffu, myidx, kb + j) + base);
                    asm volatile("cp.async.cg.shared.global [%0], [%1], 16;\n"
                                 :: "r"(sbase + (par * GRP + j) * 512u),
                                    "l"(wv + (size_t)row * 32u + lane));
                }
            }
            asm volatile("cp.async.commit_group;\n");
            asm volatile("cp.async.wait_group 1;\n" ::: "memory");

            const int cpar = (g - 1) & 1;
            const int cb   = (g - 1) * GRP;
            if (cb     < cnt) { const float4 v = mybuf[(cpar*GRP+0)*32]; a0.x+=v.x; a0.y+=v.y; a0.z+=v.z; a0.w+=v.w; }
            if (cb + 1 < cnt) { const float4 v = mybuf[(cpar*GRP+1)*32]; a1.x+=v.x; a1.y+=v.y; a1.z+=v.z; a1.w+=v.w; }
            if (cb + 2 < cnt) { const float4 v = mybuf[(cpar*GRP+2)*32]; a2.x+=v.x; a2.y+=v.y; a2.z+=v.z; a2.w+=v.w; }
            if (cb + 3 < cnt) { const float4 v = mybuf[(cpar*GRP+3)*32]; a3.x+=v.x; a3.y+=v.y; a3.z+=v.z; a3.w+=v.w; }
        }

        // ---- drain last group ----
        asm volatile("cp.async.wait_group 0;\n" ::: "memory");
        {
            const int g    = ngroups - 1;
            const int cpar = g & 1;
            const int cb   = g * GRP;
            if (cb     < cnt) { const float4 v = mybuf[(cpar*GRP+0)*32]; a0.x+=v.x; a0.y+=v.y; a0.z+=v.z; a0.w+=v.w; }
            if (cb + 1 < cnt) { const float4 v = mybuf[(cpar*GRP+1)*32]; a1.x+=v.x; a1.y+=v.y; a1.z+=v.z; a1.w+=v.w; }
            if (cb + 2 < cnt) { const float4 v = mybuf[(cpar*GRP+2)*32]; a2.x+=v.x; a2.y+=v.y; a2.z+=v.z; a2.w+=v.w; }
            if (cb + 3 < cnt) { const float4 v = mybuf[(cpar*GRP+3)*32]; a3.x+=v.x; a3.y+=v.y; a3.z+=v.z; a3.w+=v.w; }
        }
    }

    float4 acc;
    acc.x = (a0.x + a1.x) + (a2.x + a3.x);
    acc.y = (a0.y + a1.y) + (a2.y + a3.y);
    acc.z = (a0.z + a1.z) + (a2.z + a3.z);
    acc.w = (a0.w + a1.w) + (a2.w + a3.w);

    float4* o = reinterpret_cast<float4*>(
        out + (size_t)b * ((size_t)n_tables * EMB_D) + (size_t)table * EMB_D);
    o[lane] = acc;
}

extern "C" void kernel_launch(void* const* d_in, const int* in_sizes, int n_in,
                              void* d_out, int out_size)
{
    const int*   indices = (const int*)d_in[0];
    const int*   offsets = (const int*)d_in[1];
    const float* weights = (const float*)d_in[2];
    const int*   hsc     = (const int*)d_in[3];
    float* out = (float*)d_out;

    const int num_bags = in_sizes[1] - 1;   // T*B
    const int n_tables = in_sizes[3] - 1;   // T
    const int batch    = num_bags / n_tables;

    const int blocks = (num_bags + WARPS_PB - 1) / WARPS_PB;

    tbe_fwd_kernel<<<blocks, WARPS_PB * 32>>>(
        indices, offsets, weights, hsc, out, batch, n_tables, num_bags);
}

// round 7
// speedup vs baseline: 1.1847x; 1.1847x over previous
#include <cuda_runtime.h>
#include <cstdint>

// Table-batched embedding bag, SUM pooling.
// indices: int32 [T*B*L], offsets: int32 [T*B+1], weights: fp32 [T*E, 128],
// hash_size_cumsum: int32 [T+1], out: fp32 [B, T*128]
//
// One warp per bag; lane = one float4 (16B) of the 512B row.
// Row gathers via cp.async.cg into per-warp smem staging (zero data regs):
// issue 8 rows back-to-back, wait_group 0, drain from smem (thread-local
// slots, no barriers). R5 structure (flat, no pipelining - R6 showed the
// per-group commit/wait overhead loses), reshaped to 128-thread blocks +
// launch_bounds(128,12) so 12 blocks/SM co-reside (75% occ vs R5's 55%).

#define EMB_D    128
#define SLOTS    8            // rows in flight per warp per wave
#define WARPS_PB 4            // 128 threads/block; smem = 4*8*512B = 16KB

__global__ void __launch_bounds__(128, 12) tbe_fwd_kernel(
    const int*   __restrict__ indices,
    const int*   __restrict__ offsets,
    const float* __restrict__ weights,
    const int*   __restrict__ hsc,
    float*       __restrict__ out,
    int batch, int n_tables, int num_bags)
{
    // 4 warps * 8 slots * 32 lanes * 16B = 16 KB
    __shared__ float4 buf[WARPS_PB * SLOTS * 32];

    const int warp_global = (blockIdx.x * blockDim.x + threadIdx.x) >> 5;
    const int lane = threadIdx.x & 31;
    const int wib  = (threadIdx.x >> 5);
    if (warp_global >= num_bags) return;

    // this thread's private 16B staging slots: mybuf[s*32]
    float4* mybuf = buf + wib * (SLOTS * 32) + lane;
    const unsigned sbase = (unsigned)__cvta_generic_to_shared(mybuf);

    const int seg   = warp_global;
    const int table = seg / batch;
    const int b     = seg - table * batch;

    const int base  = hsc[table];          // T*E <= 4M, fits int32
    const int start = offsets[seg];
    const int end   = offsets[seg + 1];

    const float4* __restrict__ wv = reinterpret_cast<const float4*>(weights);

    float4 a0 = make_float4(0.f, 0.f, 0.f, 0.f);
    float4 a1 = make_float4(0.f, 0.f, 0.f, 0.f);
    float4 a2 = make_float4(0.f, 0.f, 0.f, 0.f);
    float4 a3 = make_float4(0.f, 0.f, 0.f, 0.f);

    for (int chunk = start; chunk < end; chunk += 32) {
        const int cnt = min(32, end - chunk);
        // one coalesced index load for up to 32 bag entries
        const int myidx = (lane < cnt) ? indices[chunk + lane] : 0;

        for (int k = 0; k < cnt; k += SLOTS) {
            const int ns = min(SLOTS, cnt - k);

            // issue up to 8 row fetches, 16B per lane, no data registers
            #pragma unroll
            for (int s = 0; s < SLOTS; s++) {
                if (s < ns) {
                    const unsigned row =
                        (unsigned)(__shfl_sync(0xffffffffu, myidx, k + s) + base);
                    asm volatile("cp.async.cg.shared.global [%0], [%1], 16;\n"
                                 :: "r"(sbase + s * 512u),
                                    "l"(wv + (size_t)row * 32u + lane));
                }
            }
            asm volatile("cp.async.commit_group;\n");
            asm volatile("cp.async.wait_group 0;\n" ::: "memory");

            // accumulate from own smem slots (thread-local, no sync needed)
            #pragma unroll
            for (int s = 0; s < SLOTS; s += 4) {
                if (s < ns) {
                    const float4 v = mybuf[s * 32];
                    a0.x += v.x; a0.y += v.y; a0.z += v.z; a0.w += v.w;
                }
                if (s + 1 < ns) {
                    const float4 v = mybuf[(s + 1) * 32];
                    a1.x += v.x; a1.y += v.y; a1.z += v.z; a1.w += v.w;
                }
                if (s + 2 < ns) {
                    const float4 v = mybuf[(s + 2) * 32];
                    a2.x += v.x; a2.y += v.y; a2.z += v.z; a2.w += v.w;
                }
                if (s + 3 < ns) {
                    const float4 v = mybuf[(s + 3) * 32];
                    a3.x += v.x; a3.y += v.y; a3.z += v.z; a3.w += v.w;
                }
            }
        }
    }

    float4 acc;
    acc.x = (a0.x + a1.x) + (a2.x + a3.x);
    acc.y = (a0.y + a1.y) + (a2.y + a3.y);
    acc.z = (a0.z + a1.z) + (a2.z + a3.z);
    acc.w = (a0.w + a1.w) + (a2.w + a3.w);

    float4* o = reinterpret_cast<float4*>(
        out + (size_t)b * ((size_t)n_tables * EMB_D) + (size_t)table * EMB_D);
    o[lane] = acc;
}

extern "C" void kernel_launch(void* const* d_in, const int* in_sizes, int n_in,
                              void* d_out, int out_size)
{
    const int*   indices = (const int*)d_in[0];
    const int*   offsets = (const int*)d_in[1];
    const float* weights = (const float*)d_in[2];
    const int*   hsc     = (const int*)d_in[3];
    float* out = (float*)d_out;

    const int num_bags = in_sizes[1] - 1;   // T*B
    const int n_tables = in_sizes[3] - 1;   // T
    const int batch    = num_bags / n_tables;

    const int blocks = (num_bags + WARPS_PB - 1) / WARPS_PB;

    tbe_fwd_kernel<<<blocks, WARPS_PB * 32>>>(
        indices, offsets, weights, hsc, out, batch, n_tables, num_bags);
}